// round 17
// baseline (speedup 1.0000x reference)
#include <cuda_runtime.h>
#include <cuda_fp16.h>
#include <math.h>
#include <cstdint>

// Problem dims (fixed)
#define BDIM 2
#define TDIM 2048
#define CDIM 1024
#define NH   16
#define HD   64
#define MROWS (BDIM*TDIM)   // 4096

// ---------------- device scratch (no allocations allowed) ----------------
__device__ float   g_q[(size_t)MROWS*CDIM];    // q after rope (fp32 natural)
__device__ float   g_k[(size_t)MROWS*HD];      // k pre-rope (fp32 natural)
__device__ __half  g_k2h[(size_t)MROWS*HD];    // k post-rope, quad-pair tiles
__device__ __half  g_vh[(size_t)MROWS*HD];     // v quad-pair tiles
__device__ __half  g_atth[(size_t)MROWS*CDIM]; // attn out, half, k-group PERMUTED
__device__ __half  g_xh[(size_t)MROWS*CDIM];   // x half, k-group PERMUTED
__device__ uint2   g_wqp[(size_t)256*CDIM];    // Wq quad-pair u2 [256][1024]
__device__ uint2   g_wop[(size_t)256*CDIM];    // Wo quad-pair u2
__device__ uint2   g_wkvp[(size_t)256*128];    // [Wk|Wv] quad-pair u2 [256][128]

// ======================= helpers =========================================
__device__ __forceinline__ void mma_f16(float* c,
    uint32_t a0, uint32_t a1, uint32_t a2, uint32_t a3,
    uint32_t b0, uint32_t b1)
{
    asm volatile(
        "mma.sync.aligned.m16n8k16.row.col.f32.f16.f16.f32 "
        "{%0,%1,%2,%3}, {%4,%5,%6,%7}, {%8,%9}, {%0,%1,%2,%3};"
        : "+f"(c[0]), "+f"(c[1]), "+f"(c[2]), "+f"(c[3])
        : "r"(a0), "r"(a1), "r"(a2), "r"(a3), "r"(b0), "r"(b1));
}
__device__ __forceinline__ uint32_t h2u(__half2 h) {
    uint32_t u; *(__half2*)&u = h; return u;
}
__device__ __forceinline__ uint32_t smem_u32(const void* p) {
    uint32_t a;
    asm("{ .reg .u64 t; cvta.to.shared.u64 t, %1; cvt.u32.u64 %0, t; }"
        : "=r"(a) : "l"(p));
    return a;
}
#define CP_ASYNC16(dst_u32, src_ptr) \
    asm volatile("cp.async.cg.shared.global [%0], [%1], 16;" \
        :: "r"(dst_u32), "l"(src_ptr) : "memory")
#define CP_COMMIT() asm volatile("cp.async.commit_group;" ::: "memory")
#define CP_WAIT0()  asm volatile("cp.async.wait_group 0;"  ::: "memory")
#define CP_WAIT1()  asm volatile("cp.async.wait_group 1;"  ::: "memory")

// =========================================================================
// Fused prep (one launch):
//   region 0: x -> permuted half (262144 groups)
//   region 1: Wq -> quad-pair u2 (65536 tasks)
//   region 2: Wo -> quad-pair u2 (65536 tasks)
//   region 3: [Wk|Wv] -> quad-pair u2 (8192 tasks)
// =========================================================================
#define PREP_X  (MROWS*CDIM/16)        // 262144
#define PREP_W  (256*256)              // 65536
#define PREP_KV (256*32)               // 8192
#define PREP_TOTAL (PREP_X + 2*PREP_W + PREP_KV)

__global__ void fused_prep_kernel(const float4* __restrict__ x,
                                  const float*  __restrict__ Wq,
                                  const float*  __restrict__ Wo,
                                  const float*  __restrict__ Wk,
                                  const float*  __restrict__ Wv,
                                  uint4* __restrict__ xh,
                                  uint4* __restrict__ wqp,
                                  uint4* __restrict__ wop,
                                  uint4* __restrict__ wkvp)
{
    int i = blockIdx.x * blockDim.x + threadIdx.x;
    if (i >= PREP_TOTAL) return;

    if (i < PREP_X) {
        float4 f0 = x[i*4+0], f1 = x[i*4+1], f2 = x[i*4+2], f3 = x[i*4+3];
        uint4 o0, o1;
        o0.x = h2u(__floats2half2_rn(f0.x, f0.y));
        o0.y = h2u(__floats2half2_rn(f2.x, f2.y));
        o0.z = h2u(__floats2half2_rn(f0.z, f0.w));
        o0.w = h2u(__floats2half2_rn(f2.z, f2.w));
        o1.x = h2u(__floats2half2_rn(f1.x, f1.y));
        o1.y = h2u(__floats2half2_rn(f3.x, f3.y));
        o1.z = h2u(__floats2half2_rn(f1.z, f1.w));
        o1.w = h2u(__floats2half2_rn(f3.z, f3.w));
        xh[i*2]   = o0;
        xh[i*2+1] = o1;
        return;
    }
    int j = i - PREP_X;
    if (j < 2*PREP_W) {
        const float* W  = (j < PREP_W) ? Wq : Wo;
        uint4*       Wp = (j < PREP_W) ? wqp : wop;
        int e = (j < PREP_W) ? j : j - PREP_W;
        int n4 = e & 255, pq = e >> 8;
        int k0 = (pq >> 2) * 16 + (pq & 3) * 2;
        const float4 a = *(const float4*)&W[(size_t)(k0    )*CDIM + n4*4];
        const float4 b = *(const float4*)&W[(size_t)(k0 + 1)*CDIM + n4*4];
        const float4 c = *(const float4*)&W[(size_t)(k0 + 8)*CDIM + n4*4];
        const float4 d = *(const float4*)&W[(size_t)(k0 + 9)*CDIM + n4*4];
        uint4 oA, oB;
        oA.x = h2u(__floats2half2_rn(a.x, b.x)); oA.y = h2u(__floats2half2_rn(c.x, d.x));
        oA.z = h2u(__floats2half2_rn(a.y, b.y)); oA.w = h2u(__floats2half2_rn(c.y, d.y));
        oB.x = h2u(__floats2half2_rn(a.z, b.z)); oB.y = h2u(__floats2half2_rn(c.z, d.z));
        oB.z = h2u(__floats2half2_rn(a.w, b.w)); oB.w = h2u(__floats2half2_rn(c.w, d.w));
        uint4* dst = Wp + ((size_t)pq * 512 + n4 * 2);
        dst[0] = oA; dst[1] = oB;
        return;
    }
    int e = j - 2*PREP_W;                 // < 8192
    int n4 = e & 15, z = (e >> 4) & 1, pq = e >> 5;
    int k0 = (pq >> 2) * 16 + (pq & 3) * 2;
    const float* src = z ? Wv : Wk;
    const float4 a = *(const float4*)&src[(size_t)(k0    )*HD + n4*4];
    const float4 b = *(const float4*)&src[(size_t)(k0 + 1)*HD + n4*4];
    const float4 c = *(const float4*)&src[(size_t)(k0 + 8)*HD + n4*4];
    const float4 d = *(const float4*)&src[(size_t)(k0 + 9)*HD + n4*4];
    uint4 oA, oB;
    oA.x = h2u(__floats2half2_rn(a.x, b.x)); oA.y = h2u(__floats2half2_rn(c.x, d.x));
    oA.z = h2u(__floats2half2_rn(a.y, b.y)); oA.w = h2u(__floats2half2_rn(c.y, d.y));
    oB.x = h2u(__floats2half2_rn(a.z, b.z)); oB.y = h2u(__floats2half2_rn(c.z, d.z));
    oB.z = h2u(__floats2half2_rn(a.w, b.w)); oB.w = h2u(__floats2half2_rn(c.w, d.w));
    uint4* dst = wkvp + ((size_t)pq * 64 + z * 32 + n4 * 2);
    dst[0] = oA; dst[1] = oB;
}

// =========================================================================
// 3-stage cp.async pipelined fp16 GEMM, ALL fragment loads LDS.64 (R16).
// =========================================================================
#define GH_ABYTES (128*32)
#define GH_BS_U2  132
#define GH_BBYTES (4*GH_BS_U2*8)
#define GH_STB (GH_ABYTES+GH_BBYTES)
#define GH_SMEM (3*GH_STB)             // 24960

__global__ void __launch_bounds__(256)
hgemm_kernel(const __half* __restrict__ A,
             const uint2* __restrict__ Bp, const float* __restrict__ bias,
             float* __restrict__ Cq,
             const uint2* __restrict__ Bkvp,
             const float* __restrict__ bk, const float* __restrict__ bv,
             float* __restrict__ Ck, __half* __restrict__ Cv)
{
    constexpr int K = CDIM;
    extern __shared__ char smc[];
    const uint32_t sbase = smem_u32(smc);

    const bool isKV = (blockIdx.x == 8);
    const int  Nq   = CDIM;

    const int tid   = threadIdx.x;
    const int lane  = tid & 31;
    const int w     = tid >> 5;
    const int warpM = w & 1;
    const int warpN = w >> 1;
    const int g     = lane >> 2;
    const int qd    = lane & 3;
    const int rowBase = blockIdx.y * 128;
    const int colBase = isKV ? 0 : blockIdx.x * 128;

    const char* gsrc[2]; uint32_t soff[2]; size_t jstr[2];
#pragma unroll
    for (int i = 0; i < 2; i++) {
        int idx = tid + i * 256;
        if (idx < 256) {
            int r = idx >> 1, c = idx & 1;
            gsrc[i] = (const char*)(A + (size_t)(rowBase + r) * K) + c * 16;
            soff[i] = (uint32_t)(r * 32 + c * 16);
            jstr[i] = 32;
        } else {
            int e = idx - 256;
            int pr = e >> 6, c = e & 63;
            const uint2* Bsel = isKV ? Bkvp : Bp;
            const int rowlen = isKV ? 128 : CDIM;
            gsrc[i] = (const char*)(Bsel + (size_t)pr * rowlen + colBase) + c * 16;
            soff[i] = (uint32_t)(GH_ABYTES + pr * (GH_BS_U2*8) + c * 16);
            jstr[i] = (size_t)4 * rowlen * 8;
        }
    }
    auto issue = [&](int j, int s) {
        const uint32_t sb = sbase + (uint32_t)s * GH_STB;
        CP_ASYNC16(sb + soff[0], gsrc[0] + (size_t)j * jstr[0]);
        CP_ASYNC16(sb + soff[1], gsrc[1] + (size_t)j * jstr[1]);
        CP_COMMIT();
    };

    const int NI = K / 16;

    float acc[4][4][4];
#pragma unroll
    for (int mt = 0; mt < 4; mt++)
#pragma unroll
        for (int nt = 0; nt < 4; nt++)
#pragma unroll
            for (int i = 0; i < 4; i++) acc[mt][nt][i] = 0.0f;

    issue(0, 0);
    issue(1, 1);

    int s = 0;
    for (int j = 0; j < NI; j++) {
        CP_WAIT1();
        __syncthreads();

        if (j + 2 < NI) {
            int s2 = s + 2; if (s2 >= 3) s2 -= 3;
            issue(j + 2, s2);
        } else {
            CP_COMMIT();
        }

        const uint2* Ah = (const uint2*)(smc + s * GH_STB);
        const uint2* Bh = (const uint2*)(smc + s * GH_STB + GH_ABYTES);

        uint2 af[4][2];
#pragma unroll
        for (int mt = 0; mt < 4; mt++) {
            const int m0 = warpM * 64 + mt * 16;
            af[mt][0] = Ah[(m0 + g    ) * 4 + qd];
            af[mt][1] = Ah[(m0 + g + 8) * 4 + qd];
        }
        uint2 bf[4];
#pragma unroll
        for (int nt = 0; nt < 4; nt++) {
            const int n0 = warpN * 32 + nt * 8;
            bf[nt] = Bh[qd * GH_BS_U2 + n0 + g];
        }
#pragma unroll
        for (int mt = 0; mt < 4; mt++)
#pragma unroll
            for (int nt = 0; nt < 4; nt++)
                mma_f16(acc[mt][nt], af[mt][0].x, af[mt][1].x,
                        af[mt][0].y, af[mt][1].y, bf[nt].x, bf[nt].y);

        if (++s == 3) s = 0;
    }

    if (!isKV) {
#pragma unroll
        for (int mt = 0; mt < 4; mt++) {
            const int row0 = rowBase + warpM * 64 + mt * 16 + g;
#pragma unroll
            for (int nt = 0; nt < 4; nt++) {
                const int c = colBase + warpN * 32 + nt * 8 + qd * 2;
                const float b0 = bias[c], b1 = bias[c + 1];
                float2 v0 = make_float2(acc[mt][nt][0] + b0, acc[mt][nt][1] + b1);
                float2 v1 = make_float2(acc[mt][nt][2] + b0, acc[mt][nt][3] + b1);
                *(float2*)&Cq[(size_t)row0 * Nq + c] = v0;
                *(float2*)&Cq[(size_t)(row0 + 8) * Nq + c] = v1;
            }
        }
    } else {
        auto wv = [&](int r, int n, float val) {
            int gt = r >> 6, rlo = r & 63;
            int kk = rlo >> 4, ww = rlo & 15, hh = ww & 1, rest = ww >> 1;
            int qd2 = rest & 3, comp = rest >> 2;
            Cv[(((size_t)gt*16 + 4*kk + qd2) * 64 + n) * 4 + comp*2 + hh] =
                __float2half_rn(val);
        };
#pragma unroll
        for (int mt = 0; mt < 4; mt++) {
            const int row0 = rowBase + warpM * 64 + mt * 16 + g;
#pragma unroll
            for (int nt = 0; nt < 4; nt++) {
                const int c = warpN * 32 + nt * 8 + qd * 2;
                if (c < 64) {
                    const float b0 = bk[c], b1 = bk[c + 1];
                    float2 v0 = make_float2(acc[mt][nt][0] + b0, acc[mt][nt][1] + b1);
                    float2 v1 = make_float2(acc[mt][nt][2] + b0, acc[mt][nt][3] + b1);
                    *(float2*)&Ck[(size_t)row0 * HD + c] = v0;
                    *(float2*)&Ck[(size_t)(row0 + 8) * HD + c] = v1;
                } else {
                    const int cv = c - 64;
                    const float b0 = bv[cv], b1 = bv[cv + 1];
                    wv(row0,     cv,     acc[mt][nt][0] + b0);
                    wv(row0,     cv + 1, acc[mt][nt][1] + b1);
                    wv(row0 + 8, cv,     acc[mt][nt][2] + b0);
                    wv(row0 + 8, cv + 1, acc[mt][nt][3] + b1);
                }
            }
        }
    }
}

// =========================================================================
// RoPE: q in-place (fp32); k -> half quad-pair tiles.
// =========================================================================
__global__ void rope_kernel(float* __restrict__ q, const float* __restrict__ kin,
                            __half* __restrict__ k2out)
{
    const int total = BDIM*TDIM*(NH+1)*(HD/2);
    int idx = blockIdx.x*blockDim.x + threadIdx.x;
    if (idx >= total) return;
    int pr   = idx & 31;
    int rest = idx >> 5;
    int hh   = rest % (NH+1);
    int bt   = rest / (NH+1);
    int t    = bt & (TDIM-1);

    float inv_freq = expf(-(float)pr * (9.2103403719761836f / 32.0f));
    float ang = (float)t * inv_freq;
    float sn, cs;
    sincosf(ang, &sn, &cs);

    if (hh < NH) {
        float* base = q + (size_t)bt*CDIM + hh*HD;
        float t1 = base[pr];
        float t2 = base[pr + 32];
        base[pr]      = t1*cs + t2*sn;
        base[pr + 32] = t1*sn - t2*cs;
    } else {
        const float* base = kin + (size_t)bt*HD;
        float t1 = base[pr];
        float t2 = base[pr + 32];
        float v1 = t1*cs + t2*sn;
        float v2 = t1*sn - t2*cs;
        int gt = bt >> 6, c = bt & 63;
        auto put = [&](int d, float val) {
            int kk = d >> 4, ww = d & 15, h = ww & 1, rr = ww >> 1;
            int qd2 = rr & 3, comp = rr >> 2;
            k2out[(((size_t)gt*16 + 4*kk + qd2)*64 + c)*4 + comp*2 + h] =
                __float2half_rn(val);
        };
        put(pr, v1);
        put(pr + 32, v2);
    }
}

// =========================================================================
// fp16 tensor-core causal MQA flash attention, BQ=128.
// 256 threads = 8 warps x 16 q-rows. Same per-warp structure as R16 but
// each CTA covers 128 q-rows -> HALF the kv-tile visits (barriers, DMA,
// softmax latency chains all halve). smem 53.2KB -> 2 CTAs/SM.
// =========================================================================
#define KVS_U2 68                     // K/V smem row stride (uint2)
#define KTILE_U2 (16*KVS_U2)          // 1088 u2 = 8704 B per tile
#define BUF_U2  (2*KTILE_U2)          // K+V per buffer = 17408 B
#define QS2 36                        // Q smem row stride (half2)
#define ATT_SMEM_BYTES (2*BUF_U2*8 + 128*QS2*4)   // 34816 + 18432 = 53248

__global__ void __launch_bounds__(256, 2)
attn_tc_kernel(const float* __restrict__ gq, const __half* __restrict__ gk2,
               const __half* __restrict__ gv2, __half* __restrict__ go)
{
    extern __shared__ float sm[];
    const uint32_t sbase = smem_u32(sm);
    __half2*  QH2 = (__half2*)((char*)sm + 2*BUF_U2*8);
    const uint32_t* QU = (const uint32_t*)QH2;

    const int qtile = (gridDim.x - 1) - blockIdx.x;   // heavy blocks first
    const int h     = blockIdx.y;
    const int b     = blockIdx.z;
    const int tid   = threadIdx.x;
    const int lane  = tid & 31;
    const int w     = tid >> 5;          // 0..7
    const int g     = lane >> 2;
    const int qd    = lane & 3;
    const int r0    = w * 16;            // local q-row base (0..112)
    const int qbase = qtile * 128;
    const unsigned FULL = 0xffffffffu;

    // tile = 16 rows x 512B (gmem) -> 544B rows (smem); K+V over 256 threads
    auto issue_tile = [&](int t, int buf) {
        const char* kgb = (const char*)gk2 + (size_t)(b*32 + t) * 8192;
        const char* vgb = (const char*)gv2 + (size_t)(b*32 + t) * 8192;
        const uint32_t kb = sbase + buf * (BUF_U2 * 8);
        const uint32_t vb = kb + KTILE_U2 * 8;
#pragma unroll
        for (int i = 0; i < 2; i++) {
            int idx = tid + i * 256;            // 0..511
            int row = idx >> 5, ch = (idx & 31) << 4;
            CP_ASYNC16(kb + row * 544 + ch, kgb + row * 512 + ch);
            CP_ASYNC16(vb + row * 544 + ch, vgb + row * 512 + ch);
        }
        CP_COMMIT();
    };

    issue_tile(0, 0);

    // ---- stage Q (scaled 1/8) as half2 k-pairs: 128 rows ----
    {
        const float* qp = gq + ((size_t)(b*TDIM + qbase))*CDIM + h*HD;
#pragma unroll
        for (int i = 0; i < 8; i++) {
            int idx = tid + i*256;              // 0..2047
            int r = idx >> 4, d4 = (idx & 15) << 2;
            float4 v = *(const float4*)(qp + (size_t)r*CDIM + d4);
            QH2[r*QS2 + (d4>>1)    ] = __floats2half2_rn(v.x*0.125f, v.y*0.125f);
            QH2[r*QS2 + (d4>>1) + 1] = __floats2half2_rn(v.z*0.125f, v.w*0.125f);
        }
    }
    __syncthreads();

    uint32_t aQ[4][4];
#pragma unroll
    for (int kk = 0; kk < 4; kk++) {
        aQ[kk][0] = QU[(r0+g  )*QS2 + 8*kk + qd    ];
        aQ[kk][1] = QU[(r0+g+8)*QS2 + 8*kk + qd    ];
        aQ[kk][2] = QU[(r0+g  )*QS2 + 8*kk + qd + 4];
        aQ[kk][3] = QU[(r0+g+8)*QS2 + 8*kk + qd + 4];
    }

    float m_[2] = {-1e30f, -1e30f};
    float l_[2] = {0.0f, 0.0f};
    float oacc[8][4];
#pragma unroll
    for (int nt = 0; nt < 8; nt++)
#pragma unroll
        for (int i = 0; i < 4; i++) oacc[nt][i] = 0.0f;

    const int nt_total = 2*qtile + 2;     // kv tiles of 64 covering 128*(qtile+1)
    for (int t = 0; t < nt_total; t++) {
        const int buf = t & 1;

        CP_WAIT0();
        __syncthreads();

        if (t + 1 < nt_total) issue_tile(t + 1, buf ^ 1);

        const uint2* KT = (const uint2*)sm + (size_t)buf * BUF_U2;
        const uint2* VT = KT + KTILE_U2;

        // ---- S = Q K^T ----
        float sacc[8][4];
#pragma unroll
        for (int nt = 0; nt < 8; nt++)
#pragma unroll
            for (int i = 0; i < 4; i++) sacc[nt][i] = 0.0f;

#pragma unroll
        for (int kk = 0; kk < 4; kk++) {
            uint2 bq[8];
#pragma unroll
            for (int nt = 0; nt < 8; nt++)
                bq[nt] = KT[(4*kk + qd)*KVS_U2 + nt*8 + g];
#pragma unroll
            for (int nt = 0; nt < 8; nt++)
                mma_f16(sacc[nt], aQ[kk][0], aQ[kk][1], aQ[kk][2], aQ[kk][3],
                        bq[nt].x, bq[nt].y);
        }

        // ---- causal mask (last two tiles only) ----
        if (t >= 2*qtile) {
            const int moff = (t - 2*qtile) * 64 - 0;   // kv offset rel. 128-row block
            const int base = moff + qd*2;              // + nt*8 below
            const int ra = r0 + g, rb = ra + 8;
#pragma unroll
            for (int nt = 0; nt < 8; nt++) {
                const int ca = base + nt*8;
                if (ca     > ra) sacc[nt][0] = -1e30f;
                if (ca + 1 > ra) sacc[nt][1] = -1e30f;
                if (ca     > rb) sacc[nt][2] = -1e30f;
                if (ca + 1 > rb) sacc[nt][3] = -1e30f;
            }
        }

        // ---- online softmax; P packed to half2 in registers ----
        uint32_t pA[8], pB[8];
#pragma unroll
        for (int rr = 0; rr < 2; rr++) {
            float lm = -1e30f;
#pragma unroll
            for (int nt = 0; nt < 8; nt++)
                lm = fmaxf(lm, fmaxf(sacc[nt][2*rr], sacc[nt][2*rr+1]));
            lm = fmaxf(lm, __shfl_xor_sync(FULL, lm, 1));
            lm = fmaxf(lm, __shfl_xor_sync(FULL, lm, 2));
            float mnew  = fmaxf(m_[rr], lm);
            float alpha = __expf(m_[rr] - mnew);

            float ls = 0.0f;
#pragma unroll
            for (int nt = 0; nt < 8; nt++) {
                float p0 = __expf(sacc[nt][2*rr]   - mnew);
                float p1 = __expf(sacc[nt][2*rr+1] - mnew);
                ls += p0 + p1;
                uint32_t pk = h2u(__floats2half2_rn(p0, p1));
                if (rr == 0) pA[nt] = pk; else pB[nt] = pk;
            }
            ls += __shfl_xor_sync(FULL, ls, 1);
            ls += __shfl_xor_sync(FULL, ls, 2);

            m_[rr] = mnew;
            l_[rr] = l_[rr]*alpha + ls;
#pragma unroll
            for (int nt = 0; nt < 8; nt++) {
                oacc[nt][2*rr]   *= alpha;
                oacc[nt][2*rr+1] *= alpha;
            }
        }

        // ---- O += P V ----
#pragma unroll
        for (int kk = 0; kk < 4; kk++) {
            uint2 bv[8];
#pragma unroll
            for (int nt = 0; nt < 8; nt++)
                bv[nt] = VT[(4*kk + qd)*KVS_U2 + nt*8 + g];
#pragma unroll
            for (int nt = 0; nt < 8; nt++)
                mma_f16(oacc[nt], pA[2*kk], pB[2*kk], pA[2*kk+1], pB[2*kk+1],
                        bv[nt].x, bv[nt].y);
        }
    }

    // ---- normalize + store as half, A-permuted k-groups ----
#pragma unroll
    for (int rr = 0; rr < 2; rr++) {
        const float inv = 1.0f / l_[rr];
        __half2* op = (__half2*)(go + ((size_t)(b*TDIM + qbase + r0 + g + rr*8))*CDIM + h*HD);
#pragma unroll
        for (int nt = 0; nt < 8; nt++) {
            op[(nt>>1)*8 + 2*qd + (nt&1)] =
                __floats2half2_rn(oacc[nt][2*rr]*inv, oacc[nt][2*rr+1]*inv);
        }
    }
}

// =========================================================================
// launch
// =========================================================================
extern "C" void kernel_launch(void* const* d_in, const int* in_sizes, int n_in,
                              void* d_out, int out_size)
{
    const float* x  = (const float*)d_in[0];
    const float* Wq = (const float*)d_in[1];
    const float* bq = (const float*)d_in[2];
    const float* Wk = (const float*)d_in[3];
    const float* bk = (const float*)d_in[4];
    const float* Wv = (const float*)d_in[5];
    const float* bv = (const float*)d_in[6];
    const float* Wo = (const float*)d_in[7];
    const float* bo = (const float*)d_in[8];
    float* out = (float*)d_out;

    float *qp, *kp;
    __half *k2p, *vp, *ap, *xh;
    uint2 *wqp, *wop, *wkvp;
    cudaGetSymbolAddress((void**)&qp,   g_q);
    cudaGetSymbolAddress((void**)&kp,   g_k);
    cudaGetSymbolAddress((void**)&k2p,  g_k2h);
    cudaGetSymbolAddress((void**)&vp,   g_vh);
    cudaGetSymbolAddress((void**)&ap,   g_atth);
    cudaGetSymbolAddress((void**)&xh,   g_xh);
    cudaGetSymbolAddress((void**)&wqp,  g_wqp);
    cudaGetSymbolAddress((void**)&wop,  g_wop);
    cudaGetSymbolAddress((void**)&wkvp, g_wkvp);

    cudaFuncSetAttribute(hgemm_kernel,
        cudaFuncAttributeMaxDynamicSharedMemorySize, GH_SMEM);
    cudaFuncSetAttribute(attn_tc_kernel,
        cudaFuncAttributeMaxDynamicSharedMemorySize, ATT_SMEM_BYTES);

    // one fused prep launch
    fused_prep_kernel<<<(PREP_TOTAL + 255)/256, 256>>>(
        (const float4*)x, Wq, Wo, Wk, Wv,
        (uint4*)xh, (uint4*)wqp, (uint4*)wop, (uint4*)wkvp);

    // Q = x@Wq+bq  AND  K/V = x@[Wk|Wv]+b  in ONE fp16 launch (tile x==8 -> KV)
    hgemm_kernel<<<dim3(9, MROWS/128), 256, GH_SMEM>>>(
        xh, wqp, bq, qp,  wkvp, bk, bv, kp, vp);

    // RoPE: q in-place, k natural -> quad-pair half tiles
    {
        int total = BDIM*TDIM*(NH+1)*(HD/2);
        rope_kernel<<<(total + 255)/256, 256>>>(qp, kp, k2p);
    }

    // causal MQA attention (fp16, BQ=128) -> permuted half att
    attn_tc_kernel<<<dim3(TDIM/128, NH, BDIM), 256, ATT_SMEM_BYTES>>>(
        qp, k2p, vp, ap);

    // out = att @ Wo + bo  (fp16 GEMM; att already permuted half)
    hgemm_kernel<<<dim3(8, MROWS/128), 256, GH_SMEM>>>(
        ap, wop, bo, out,  wkvp, bk, bv, kp, vp);   // KV path unused (grid.x=8)
}